// round 6
// baseline (speedup 1.0000x reference)
#include <cuda_runtime.h>
#include <math.h>

#define EPSN 1e-12f

// One CTA = one (n, h, x-tile of TX). Loads L tile (C x TX) and R halo tile
// (C x SRP, SRP >= TX + D - 1) into shared, computes per-column inverse L2
// norms in shared, then banded Gram products with RD x RX register blocking.
// Normalization applied in the epilogue:
//   out[d][x] = (sum_c L[c][x] * R[c][x-d]) * invl[x] * invr[x-d]
//
// RX == 4: per-thread shared loads are single float4s with warp lane stride
// exactly one float4 => fully coalesced, conflict-free LDS.128 on both tiles.
// RD = 16 raises intensity to 64 FMA per 96 LDS bytes (FMA-pipe bound).

template<int C, int D, int TX, int RD, int RX, int SRP, int NT>
__global__ __launch_bounds__(NT, 2)
void cost_volume_kernel(const float* __restrict__ Lp,
                        const float* __restrict__ Rp,
                        float* __restrict__ out,
                        int H, int W)
{
    static_assert(RX == 4, "RX must be 4 (float4 lane-contiguous LDS)");
    static_assert(TX % RX == 0 && D % RD == 0, "tiling");
    static_assert((D / RD) * (TX / RX) == NT, "thread count");
    static_assert(SRP % 4 == 0 && SRP >= TX + D - 1, "R halo row");

    extern __shared__ float smem[];
    float* sl   = smem;                 // C * TX
    float* sr   = smem + C * TX;        // C * SRP
    float* invl = sr + C * SRP;         // TX
    float* invr = invl + TX;            // SRP

    const int n   = blockIdx.z;
    const int h   = blockIdx.y;
    const int xb  = blockIdx.x * TX;
    const int tid = threadIdx.x;

    const int plane = ((n * C) * H + h) * W;
    const int HW = H * W;

    // ---- cooperative tile loads (rows are contiguous in gmem) ----
    #pragma unroll 1
    for (int idx = tid; idx < C * TX; idx += NT) {
        int c = idx / TX, x = idx % TX;
        sl[idx] = Lp[plane + c * HW + xb + x];
    }
    const int y0 = xb - (D - 1);
    #pragma unroll 1
    for (int idx = tid; idx < C * SRP; idx += NT) {
        int c = idx / SRP, col = idx % SRP;
        int y = y0 + col;
        sr[idx] = (y >= 0 && y < W) ? Rp[plane + c * HW + y] : 0.0f;
    }
    __syncthreads();

    // ---- per-column inverse norms (lane stride 1 => conflict-free) ----
    for (int t = tid; t < TX; t += NT) {
        float ss = 0.0f;
        #pragma unroll
        for (int c = 0; c < C; ++c) { float v = sl[c * TX + t]; ss = fmaf(v, v, ss); }
        invl[t] = 1.0f / fmaxf(sqrtf(ss), EPSN);
    }
    for (int t = tid; t < SRP; t += NT) {
        float ss = 0.0f;
        #pragma unroll
        for (int c = 0; c < C; ++c) { float v = sr[c * SRP + t]; ss = fmaf(v, v, ss); }
        invr[t] = 1.0f / fmaxf(sqrtf(ss), EPSN);
    }
    __syncthreads();

    // ---- register-blocked banded products ----
    constexpr int BX = TX / RX;
    const int tx = tid % BX;
    const int td = tid / BX;
    const int x0 = tx * RX;                 // multiple of 4
    const int d0 = td * RD;
    // sr column for (x = x0+j, d = d0+i) is x0 + j + (D-1) - d0 - i.
    const int rbase = x0 + (D - 1) - d0 - (RD - 1);   // multiple of 4 (checked per level)

    float acc[RD][RX];
    #pragma unroll
    for (int i = 0; i < RD; ++i)
        #pragma unroll
        for (int j = 0; j < RX; ++j) acc[i][j] = 0.0f;

    constexpr int NV  = RX + RD - 1;        // distinct r values needed
    constexpr int NR4 = (NV + 3) / 4;       // float4 loads

    #pragma unroll 2
    for (int c = 0; c < C; ++c) {
        float lv[RX];
        *(float4*)lv = *(const float4*)&sl[c * TX + x0];
        float rv[NR4 * 4];
        #pragma unroll
        for (int q = 0; q < NR4; ++q)
            *(float4*)&rv[q * 4] = *(const float4*)&sr[c * SRP + rbase + q * 4];
        #pragma unroll
        for (int i = 0; i < RD; ++i)
            #pragma unroll
            for (int j = 0; j < RX; ++j)
                acc[i][j] = fmaf(lv[j], rv[j + (RD - 1 - i)], acc[i][j]);
    }

    // ---- epilogue: normalize, mask x<d, streaming float4 stores ----
    #pragma unroll
    for (int i = 0; i < RD; ++i) {
        const int d = d0 + i;
        float4 o;
        float* op = (float*)&o;
        #pragma unroll
        for (int j = 0; j < RX; ++j) {
            const int xg  = xb + x0 + j;
            const int col = x0 + j + (D - 1) - d;
            op[j] = (xg >= d) ? acc[i][j] * invl[x0 + j] * invr[col] : 0.0f;
        }
        __stcs((float4*)&out[((n * D + d) * H + h) * W + xb + x0], o);
    }
}

extern "C" void kernel_launch(void* const* d_in, const int* in_sizes, int n_in,
                              void* d_out, int out_size)
{
    const float* l0 = (const float*)d_in[0];
    const float* r0 = (const float*)d_in[1];
    const float* l1 = (const float*)d_in[2];
    const float* r1 = (const float*)d_in[3];
    const float* l2 = (const float*)d_in[4];
    const float* r2 = (const float*)d_in[5];
    float* out = (float*)d_out;

    // max_disparity = 128 (fixed by setup_inputs); per-level D = 128, 64, 32.

    // ---- level 0: (2, 32, 256, 512), D=128 ----
    {
        constexpr int C = 32, D = 128, TX = 128, RD = 16, RX = 4;
        constexpr int SRP = 256;                       // >= 255, mult of 4
        constexpr int NT  = (D / RD) * (TX / RX);      // 8 * 32 = 256
        constexpr size_t SM = (size_t)(C * TX + C * SRP + TX + SRP) * sizeof(float); // 50.7 KB
        auto k = cost_volume_kernel<C, D, TX, RD, RX, SRP, NT>;
        cudaFuncSetAttribute(k, cudaFuncAttributeMaxDynamicSharedMemorySize, (int)SM);
        k<<<dim3(512 / TX, 256, 2), NT, SM>>>(l0, r0, out, 256, 512);
    }

    // ---- level 1: (2, 64, 128, 256), D=64 ----
    {
        constexpr int C = 64, D = 64, TX = 128, RD = 16, RX = 4;
        constexpr int SRP = 192;                       // >= 191, mult of 4
        constexpr int NT  = (D / RD) * (TX / RX);      // 4 * 32 = 128
        constexpr size_t SM = (size_t)(C * TX + C * SRP + TX + SRP) * sizeof(float); // 83.2 KB
        auto k = cost_volume_kernel<C, D, TX, RD, RX, SRP, NT>;
        cudaFuncSetAttribute(k, cudaFuncAttributeMaxDynamicSharedMemorySize, (int)SM);
        float* out1 = out + (size_t)2 * 128 * 256 * 512;
        k<<<dim3(256 / TX, 128, 2), NT, SM>>>(l1, r1, out1, 128, 256);
    }

    // ---- level 2: (2, 96, 64, 128), D=32 — small tiles for parallelism ----
    {
        constexpr int C = 96, D = 32, TX = 32, RD = 4, RX = 4;
        constexpr int SRP = 64;                        // >= 63, mult of 4
        constexpr int NT  = (D / RD) * (TX / RX);      // 8 * 8 = 64
        constexpr size_t SM = (size_t)(C * TX + C * SRP + TX + SRP) * sizeof(float); // 37.5 KB
        auto k = cost_volume_kernel<C, D, TX, RD, RX, SRP, NT>;
        cudaFuncSetAttribute(k, cudaFuncAttributeMaxDynamicSharedMemorySize, (int)SM);
        float* out2 = out + (size_t)2 * 128 * 256 * 512 + (size_t)2 * 64 * 128 * 256;
        k<<<dim3(128 / TX, 64, 2), NT, SM>>>(l2, r2, out2, 64, 128);
    }
}

// round 7
// speedup vs baseline: 1.5570x; 1.5570x over previous
#include <cuda_runtime.h>
#include <math.h>

#define EPSN 1e-12f

// ---------- packed fp32x2 helpers (sm_10x) ----------
__device__ __forceinline__ unsigned long long fma2(unsigned long long a,
                                                   unsigned long long b,
                                                   unsigned long long c) {
    unsigned long long d;
    asm("fma.rn.f32x2 %0, %1, %2, %3;" : "=l"(d) : "l"(a), "l"(b), "l"(c));
    return d;
}
__device__ __forceinline__ unsigned long long mkpair(float lo, float hi) {
    unsigned long long p;
    asm("mov.b64 %0, {%1, %2};" : "=l"(p) : "f"(lo), "f"(hi));
    return p;
}
__device__ __forceinline__ void unpair(unsigned long long p, float& lo, float& hi) {
    asm("mov.b64 {%0, %1}, %2;" : "=f"(lo), "=f"(hi) : "l"(p));
}

// One CTA = one (n, h, x-tile of TX). Channels processed in passes of CB
// (tiles of CB channels staged in smem; output accumulators and per-column
// sum-of-squares partials live in registers across passes). Per-column
// inverse L2 norms are applied only in the epilogue:
//   out[d][x] = (sum_c L[c][x] * R[c][x-d]) * invl[x] * invr[x-d]
// RX is fixed at 4: per-thread shared loads are single float4s with warp
// lane stride exactly one float4 => conflict-free LDS.128 on both tiles.
// Inner products use packed fma.rn.f32x2 (2 FMAs/instr) to halve FMA issue.

template<int C, int CB, int D, int TX, int RD, int SRP, int NT, int MINB>
__global__ __launch_bounds__(NT, MINB)
void cost_volume_kernel(const float* __restrict__ Lp,
                        const float* __restrict__ Rp,
                        float* __restrict__ out,
                        int H, int W)
{
    constexpr int RX = 4;
    static_assert(C % CB == 0, "channel split");
    static_assert(TX % RX == 0 && D % RD == 0 && (RD % 2) == 0, "tiling");
    static_assert((D / RD) * (TX / RX) == NT, "thread count");
    static_assert(SRP % 4 == 0 && SRP >= TX + D - 1, "R halo row");

    extern __shared__ float smem[];
    float* sl   = smem;                  // CB * TX
    float* sr   = smem + CB * TX;        // CB * SRP
    float* invl = sr + CB * SRP;         // TX
    float* invr = invl + TX;             // SRP

    const int n   = blockIdx.z;
    const int h   = blockIdx.y;
    const int xb  = blockIdx.x * TX;
    const int tid = threadIdx.x;

    const int plane = ((n * C) * H + h) * W;
    const int HW = H * W;
    const int y0 = xb - (D - 1);

    // thread -> (d-block, x-block)
    constexpr int BX = TX / RX;
    const int x0 = (tid % BX) * RX;                 // multiple of 4
    const int d0 = (tid / BX) * RD;
    const int rbase = x0 + (D - 1) - d0 - (RD - 1); // multiple of 4 by construction

    constexpr int NV  = RX + RD - 1;
    constexpr int NR4 = (NV + 3) / 4;

    // accumulators (packed pairs) + per-column sum-of-squares partials
    unsigned long long acc[RD][2];
    #pragma unroll
    for (int i = 0; i < RD; ++i) { acc[i][0] = 0ull; acc[i][1] = 0ull; }

    constexpr int NSL = (TX  + NT - 1) / NT;
    constexpr int NSR = (SRP + NT - 1) / NT;
    float ssl[NSL], ssr[NSR];
    #pragma unroll
    for (int k = 0; k < NSL; ++k) ssl[k] = 0.0f;
    #pragma unroll
    for (int k = 0; k < NSR; ++k) ssr[k] = 0.0f;

    #pragma unroll 1
    for (int c0 = 0; c0 < C; c0 += CB) {
        if (c0) __syncthreads();   // previous pass finished reading tiles

        // ---- stage CB channels of L and R-halo (rows contiguous in gmem) ----
        #pragma unroll 1
        for (int idx = tid; idx < CB * TX; idx += NT) {
            int c = idx / TX, x = idx % TX;
            sl[idx] = Lp[plane + (c0 + c) * HW + xb + x];
        }
        #pragma unroll 1
        for (int idx = tid; idx < CB * SRP; idx += NT) {
            int c = idx / SRP, col = idx % SRP;
            int y = y0 + col;
            sr[idx] = (y >= 0 && y < W) ? Rp[plane + (c0 + c) * HW + y] : 0.0f;
        }
        __syncthreads();

        // ---- accumulate per-column sum of squares (lane stride 1) ----
        #pragma unroll
        for (int k = 0; k < NSL; ++k) {
            int t = tid + k * NT;
            if (t < TX) {
                float ss = ssl[k];
                #pragma unroll
                for (int c = 0; c < CB; ++c) { float v = sl[c * TX + t]; ss = fmaf(v, v, ss); }
                ssl[k] = ss;
            }
        }
        #pragma unroll
        for (int k = 0; k < NSR; ++k) {
            int t = tid + k * NT;
            if (t < SRP) {
                float ss = ssr[k];
                #pragma unroll
                for (int c = 0; c < CB; ++c) { float v = sr[c * SRP + t]; ss = fmaf(v, v, ss); }
                ssr[k] = ss;
            }
        }

        // ---- main banded-product loop (packed f32x2 FMAs) ----
        #pragma unroll 4
        for (int c = 0; c < CB; ++c) {
            union { float4 q; unsigned long long u[2]; } lq;
            lq.q = *(const float4*)&sl[c * TX + x0];

            union { float4 q[NR4]; unsigned long long u[NR4 * 2]; float f[NR4 * 4]; } rq;
            #pragma unroll
            for (int q = 0; q < NR4; ++q)
                rq.q[q] = *(const float4*)&sr[c * SRP + rbase + 4 * q];

            #pragma unroll
            for (int i = 0; i < RD; ++i) {
                const int s = RD - 1 - i;   // rv shift for this d
                unsigned long long b0, b1;
                if ((s & 1) == 0) {         // aligned pairs: free reinterpret
                    b0 = rq.u[s / 2];
                    b1 = rq.u[s / 2 + 1];
                } else {                     // odd shift: build pairs (CSE'd movs)
                    b0 = mkpair(rq.f[s],     rq.f[s + 1]);
                    b1 = mkpair(rq.f[s + 2], rq.f[s + 3]);
                }
                acc[i][0] = fma2(lq.u[0], b0, acc[i][0]);
                acc[i][1] = fma2(lq.u[1], b1, acc[i][1]);
            }
        }
    }

    // ---- finalize inverse norms (owner thread computes its own columns) ----
    #pragma unroll
    for (int k = 0; k < NSL; ++k) {
        int t = tid + k * NT;
        if (t < TX) invl[t] = 1.0f / fmaxf(sqrtf(ssl[k]), EPSN);
    }
    #pragma unroll
    for (int k = 0; k < NSR; ++k) {
        int t = tid + k * NT;
        if (t < SRP) invr[t] = 1.0f / fmaxf(sqrtf(ssr[k]), EPSN);
    }
    __syncthreads();

    // ---- epilogue: normalize, mask x<d, streaming float4 stores ----
    #pragma unroll
    for (int i = 0; i < RD; ++i) {
        const int d = d0 + i;
        float a[RX];
        unpair(acc[i][0], a[0], a[1]);
        unpair(acc[i][1], a[2], a[3]);
        float4 o;
        float* op = (float*)&o;
        #pragma unroll
        for (int j = 0; j < RX; ++j) {
            const int xg  = xb + x0 + j;
            const int col = x0 + j + (D - 1) - d;
            op[j] = (xg >= d) ? a[j] * invl[x0 + j] * invr[col] : 0.0f;
        }
        __stcs((float4*)&out[((n * D + d) * H + h) * W + xb + x0], o);
    }
}

extern "C" void kernel_launch(void* const* d_in, const int* in_sizes, int n_in,
                              void* d_out, int out_size)
{
    const float* l0 = (const float*)d_in[0];
    const float* r0 = (const float*)d_in[1];
    const float* l1 = (const float*)d_in[2];
    const float* r1 = (const float*)d_in[3];
    const float* l2 = (const float*)d_in[4];
    const float* r2 = (const float*)d_in[5];
    float* out = (float*)d_out;

    // max_disparity = 128 (fixed by setup_inputs); per-level D = 128, 64, 32.

    // ---- level 0: (2, 32, 256, 512), D=128 : 2 CTAs x 512 thr / SM ----
    {
        constexpr int C = 32, CB = 32, D = 128, TX = 128, RD = 8, SRP = 256;
        constexpr int NT = (D / RD) * (TX / 4);        // 512
        constexpr size_t SM = (size_t)(CB * TX + CB * SRP + TX + SRP) * sizeof(float); // 50.7 KB
        auto k = cost_volume_kernel<C, CB, D, TX, RD, SRP, NT, 2>;
        cudaFuncSetAttribute(k, cudaFuncAttributeMaxDynamicSharedMemorySize, (int)SM);
        k<<<dim3(512 / TX, 256, 2), NT, SM>>>(l0, r0, out, 256, 512);
    }

    // ---- level 1: (2, 64, 128, 256), D=64 : CB=32 split, 4 CTAs x 256 / SM ----
    {
        constexpr int C = 64, CB = 32, D = 64, TX = 128, RD = 8, SRP = 192;
        constexpr int NT = (D / RD) * (TX / 4);        // 256
        constexpr size_t SM = (size_t)(CB * TX + CB * SRP + TX + SRP) * sizeof(float); // 41.3 KB
        auto k = cost_volume_kernel<C, CB, D, TX, RD, SRP, NT, 4>;
        cudaFuncSetAttribute(k, cudaFuncAttributeMaxDynamicSharedMemorySize, (int)SM);
        float* out1 = out + (size_t)2 * 128 * 256 * 512;
        k<<<dim3(256 / TX, 128, 2), NT, SM>>>(l1, r1, out1, 128, 256);
    }

    // ---- level 2: (2, 96, 64, 128), D=32 : CB=32 split, 8 CTAs x 128 / SM ----
    {
        constexpr int C = 96, CB = 32, D = 32, TX = 64, RD = 4, SRP = 96;
        constexpr int NT = (D / RD) * (TX / 4);        // 128
        constexpr size_t SM = (size_t)(CB * TX + CB * SRP + TX + SRP) * sizeof(float); // 20.6 KB
        auto k = cost_volume_kernel<C, CB, D, TX, RD, SRP, NT, 8>;
        cudaFuncSetAttribute(k, cudaFuncAttributeMaxDynamicSharedMemorySize, (int)SM);
        float* out2 = out + (size_t)2 * 128 * 256 * 512 + (size_t)2 * 64 * 128 * 256;
        k<<<dim3(128 / TX, 64, 2), NT, SM>>>(l2, r2, out2, 64, 128);
    }
}